// round 4
// baseline (speedup 1.0000x reference)
#include <cuda_runtime.h>
#include <math.h>

// Problem constants (fixed shapes per reference)
#define NN 400000
#define EE 3200000
#define S_SEG 1200
#define B_IMG 8

// ---------------- device scratch (static globals; no allocation) ----------------
__device__ __align__(16) float  g_bufA[(size_t)NN * 64];   // h (post-agg, pre-BN-affine)
__device__ __align__(16) float  g_bufB[(size_t)NN * 64];   // t * dis[node]
__device__ float  g_dis[NN];                 // rsqrt(deg)
__device__ int    g_degi[NN];                // integer in-degree (excl self-loop)
__device__ int    g_rowptr[NN + 1];
__device__ int    g_cursor[NN];
__device__ int    g_csr[EE];                 // src indices grouped by dst
__device__ int    g_bsums[512];
__device__ double g_stats[128];              // per-channel sum / sumsq
__device__ float  g_scale[64];
__device__ float  g_shift[64];
__device__ float  g_segfeat[S_SEG * 256];    // [mean|min|max|std] per segment
__device__ float  g_proj[S_SEG * 64];

// ---------------- degree / CSR build ----------------
__global__ void k_zero_nodes(int n) {
    int i = blockIdx.x * blockDim.x + threadIdx.x;
    if (i < n) { g_degi[i] = 0; g_cursor[i] = 0; }
    if (blockIdx.x == 0 && threadIdx.x < 128) g_stats[threadIdx.x] = 0.0;
}
__global__ void k_deg_count(const int* __restrict__ dst, int e) {
    int i = blockIdx.x * blockDim.x + threadIdx.x;
    if (i < e) atomicAdd(&g_degi[dst[i]], 1);
}
__global__ void k_deg_fin(int n) {
    int i = blockIdx.x * blockDim.x + threadIdx.x;
    if (i < n) g_dis[i] = rsqrtf((float)(g_degi[i] + 1));  // +1 self loop
}

#define SCAN_CHUNK 1024
// block-local exclusive scan of degi -> rowptr, block totals to g_bsums
__global__ void k_scan1(int n) {
    __shared__ int sh[256];
    int base = blockIdx.x * SCAN_CHUNK;
    int t = threadIdx.x;
    int v[4]; int loc = 0;
    #pragma unroll
    for (int k = 0; k < 4; k++) {
        int i = base + t * 4 + k;
        v[k] = (i < n) ? g_degi[i] : 0;
        loc += v[k];
    }
    sh[t] = loc;
    __syncthreads();
    for (int off = 1; off < 256; off <<= 1) {
        int x = sh[t];
        int y = (t >= off) ? sh[t - off] : 0;
        __syncthreads();
        sh[t] = x + y;
        __syncthreads();
    }
    int excl = (t == 0) ? 0 : sh[t - 1];
    if (t == 255) g_bsums[blockIdx.x] = sh[255];
    int run = excl;
    #pragma unroll
    for (int k = 0; k < 4; k++) {
        int i = base + t * 4 + k;
        if (i < n) g_rowptr[i] = run;
        run += v[k];
    }
}
__global__ void k_scan2(int nb) {
    __shared__ int sh[512];
    int t = threadIdx.x;
    sh[t] = (t < nb) ? g_bsums[t] : 0;
    __syncthreads();
    for (int off = 1; off < 512; off <<= 1) {
        int x = sh[t];
        int y = (t >= off) ? sh[t - off] : 0;
        __syncthreads();
        sh[t] = x + y;
        __syncthreads();
    }
    if (t < nb) g_bsums[t] = (t == 0) ? 0 : sh[t - 1];
}
__global__ void k_scan3(int n, int e) {
    int base = blockIdx.x * SCAN_CHUNK;
    int add = g_bsums[blockIdx.x];
    int t = threadIdx.x;
    #pragma unroll
    for (int k = 0; k < 4; k++) {
        int i = base + t * 4 + k;
        if (i < n) g_rowptr[i] += add;
    }
    if (blockIdx.x == 0 && t == 0) g_rowptr[n] = e;
}
__global__ void k_fill(const int* __restrict__ src, const int* __restrict__ dst, int e) {
    int i = blockIdx.x * blockDim.x + threadIdx.x;
    if (i < e) {
        int d = dst[i];
        int p = atomicAdd(&g_cursor[d], 1);
        g_csr[g_rowptr[d] + p] = src[i];
    }
}

// ---------------- GEMM: t~ = (act(affine(h)) @ W) * dis[node] ----------------
template<int FI, int FO, bool BN>
__global__ void k_gemm(const float* __restrict__ xin, const float* __restrict__ W, int n) {
    constexpr int NPB = 256 / FO;
    __shared__ float Ws[FI * FO];
    __shared__ float xs[NPB * FI];
    int tid = threadIdx.x;
    for (int i = tid; i < FI * FO; i += 256) Ws[i] = W[i];
    int base = blockIdx.x * NPB;
    for (int i = tid; i < NPB * FI; i += 256) {
        int ln = i / FI, k = i - ln * FI;
        int node = base + ln;
        float v = 0.f;
        if (node < n) {
            if (BN) {
                v = g_bufA[(size_t)node * FI + k];
                v = fmaxf(fmaf(g_scale[k], v, g_shift[k]), 0.f);
            } else {
                v = xin[(size_t)node * FI + k];
            }
        }
        xs[i] = v;
    }
    __syncthreads();
    int c = tid % FO, ln = tid / FO;
    int node = base + ln;
    if (node < n) {
        float acc = 0.f;
        #pragma unroll
        for (int k = 0; k < FI; k++)
            acc = fmaf(xs[ln * FI + k], Ws[k * FO + c], acc);
        g_bufB[(size_t)node * FO + c] = acc * g_dis[node];
    }
}

// ---------------- CSR gather (group variant, FO=32/64) ----------------
// TPN lanes per node. Indices prefetched by all lanes in one parallel round,
// broadcast via shfl; data gathers become independent loads (high MLP).
template<int FO>
__global__ void k_agg_grp(int n) {
    constexpr int TPN = FO / 4;        // 8 or 16 threads per node (float4 each)
    constexpr int NPB = 256 / TPN;
    __shared__ float ss[64], ss2[64];
    int tid = threadIdx.x;
    if (tid < FO) { ss[tid] = 0.f; ss2[tid] = 0.f; }
    __syncthreads();
    int grp = tid / TPN, lane = tid % TPN;
    int lw = tid & 31;
    int gbase = lw & ~(TPN - 1);
    unsigned gmask = ((TPN == 32) ? 0xFFFFFFFFu : ((1u << TPN) - 1u)) << gbase;
    const float4* in = (const float4*)g_bufB;
    float4* outb = (float4*)g_bufA;
    float l0 = 0, l1 = 0, l2 = 0, l3 = 0, m0 = 0, m1 = 0, m2 = 0, m3 = 0;
    for (int d = blockIdx.x * NPB + grp; d < n; d += gridDim.x * NPB) {
        float4 acc = in[(size_t)d * TPN + lane];   // self-loop term
        int beg = g_rowptr[d], end = g_rowptr[d + 1];
        for (int rb = beg; rb < end; rb += TPN) {
            int cnt = end - rb; if (cnt > TPN) cnt = TPN;
            int q = rb + lane;
            int myidx = g_csr[q < end ? q : end - 1];
            for (int j = 0; j < cnt; j++) {
                int s = __shfl_sync(gmask, myidx, gbase + j, 32);
                float4 v = in[(size_t)s * TPN + lane];
                acc.x += v.x; acc.y += v.y; acc.z += v.z; acc.w += v.w;
            }
        }
        float dd = g_dis[d];
        acc.x *= dd; acc.y *= dd; acc.z *= dd; acc.w *= dd;
        outb[(size_t)d * TPN + lane] = acc;
        l0 += acc.x; l1 += acc.y; l2 += acc.z; l3 += acc.w;
        m0 += acc.x * acc.x; m1 += acc.y * acc.y;
        m2 += acc.z * acc.z; m3 += acc.w * acc.w;
    }
    int c = lane * 4;
    atomicAdd(&ss[c + 0], l0); atomicAdd(&ss2[c + 0], m0);
    atomicAdd(&ss[c + 1], l1); atomicAdd(&ss2[c + 1], m1);
    atomicAdd(&ss[c + 2], l2); atomicAdd(&ss2[c + 2], m2);
    atomicAdd(&ss[c + 3], l3); atomicAdd(&ss2[c + 3], m3);
    __syncthreads();
    if (tid < FO) {
        atomicAdd(&g_stats[tid], (double)ss[tid]);
        atomicAdd(&g_stats[64 + tid], (double)ss2[tid]);
    }
}

// ---------------- CSR gather (thread-per-node variant, FO=8/16) ----------------
template<int FO>
__global__ void k_agg_tpn(int n) {
    constexpr int NF4 = FO / 4;        // 2 or 4 float4 per row
    __shared__ float ss[64], ss2[64];
    int tid = threadIdx.x;
    if (tid < FO) { ss[tid] = 0.f; ss2[tid] = 0.f; }
    __syncthreads();
    const float4* in = (const float4*)g_bufB;
    float4* outb = (float4*)g_bufA;
    float ls[FO], ls2[FO];
    #pragma unroll
    for (int c = 0; c < FO; c++) { ls[c] = 0.f; ls2[c] = 0.f; }
    for (int d = blockIdx.x * 256 + tid; d < n; d += gridDim.x * 256) {
        float4 acc[NF4];
        #pragma unroll
        for (int f = 0; f < NF4; f++) acc[f] = in[(size_t)d * NF4 + f];
        int beg = g_rowptr[d], end = g_rowptr[d + 1];
        for (int rb = beg; rb < end; rb += 8) {
            int cnt = end - rb; if (cnt > 8) cnt = 8;
            int idx[8];
            #pragma unroll
            for (int j = 0; j < 8; j++) {
                int q = rb + j;
                idx[j] = g_csr[q < end ? q : end - 1];
            }
            #pragma unroll
            for (int j = 0; j < 8; j++) {
                if (j < cnt) {
                    #pragma unroll
                    for (int f = 0; f < NF4; f++) {
                        float4 v = in[(size_t)idx[j] * NF4 + f];
                        acc[f].x += v.x; acc[f].y += v.y;
                        acc[f].z += v.z; acc[f].w += v.w;
                    }
                }
            }
        }
        float dd = g_dis[d];
        #pragma unroll
        for (int f = 0; f < NF4; f++) {
            acc[f].x *= dd; acc[f].y *= dd; acc[f].z *= dd; acc[f].w *= dd;
            outb[(size_t)d * NF4 + f] = acc[f];
            ls[f * 4 + 0] += acc[f].x;  ls2[f * 4 + 0] += acc[f].x * acc[f].x;
            ls[f * 4 + 1] += acc[f].y;  ls2[f * 4 + 1] += acc[f].y * acc[f].y;
            ls[f * 4 + 2] += acc[f].z;  ls2[f * 4 + 2] += acc[f].z * acc[f].z;
            ls[f * 4 + 3] += acc[f].w;  ls2[f * 4 + 3] += acc[f].w * acc[f].w;
        }
    }
    #pragma unroll
    for (int c = 0; c < FO; c++) {
        atomicAdd(&ss[c], ls[c]);
        atomicAdd(&ss2[c], ls2[c]);
    }
    __syncthreads();
    if (tid < FO) {
        atomicAdd(&g_stats[tid], (double)ss[tid]);
        atomicAdd(&g_stats[64 + tid], (double)ss2[tid]);
    }
}

// scale = g*rsqrt(var+eps); shift = be - scale*mean   (bias b cancels in BN)
// Also zeroes g_stats for the next layer.
__global__ void k_bnfin(const float* __restrict__ g, const float* __restrict__ be,
                        int n, int fo) {
    int c = threadIdx.x;
    if (c >= 64) return;
    double s  = g_stats[c];
    double s2 = g_stats[64 + c];
    g_stats[c] = 0.0; g_stats[64 + c] = 0.0;
    if (c < fo) {
        double mean = s / n;
        double var  = s2 / n - mean * mean;
        float rs = rsqrtf((float)var + 1e-5f);
        float sc = g[c] * rs;
        g_scale[c] = sc;
        g_shift[c] = be[c] - sc * (float)mean;
    }
}

// ---------------- segment multi-aggregation (batch_idx sorted) ----------------
__global__ void k_segagg(const int* __restrict__ bidx, int n) {
    int s = blockIdx.x;   // 0..S_SEG-1
    int tid = threadIdx.x;
    int c = tid & 63, rr = tid >> 6;     // 4 row groups x 64 channels
    int lo = 0, hi = n;
    while (lo < hi) { int m = (lo + hi) >> 1; if (bidx[m] < s) lo = m + 1; else hi = m; }
    int start = lo;
    hi = n;
    while (lo < hi) { int m = (lo + hi) >> 1; if (bidx[m] < s + 1) lo = m + 1; else hi = m; }
    int end = lo;
    float sc = g_scale[c], sh = g_shift[c];
    double sum = 0.0, sum2 = 0.0;
    float mn = INFINITY, mx = -INFINITY;
    for (int r = start + rr; r < end; r += 4) {
        float v = fmaf(sc, g_bufA[(size_t)r * 64 + c], sh);
        sum += v; sum2 += (double)v * v;
        mn = fminf(mn, v); mx = fmaxf(mx, v);
    }
    __shared__ double s1[256], s2[256];
    __shared__ float smn[256], smx[256];
    s1[tid] = sum; s2[tid] = sum2; smn[tid] = mn; smx[tid] = mx;
    __syncthreads();
    if (rr == 0) {
        #pragma unroll
        for (int k = 1; k < 4; k++) {
            sum += s1[tid + 64 * k]; sum2 += s2[tid + 64 * k];
            mn = fminf(mn, smn[tid + 64 * k]); mx = fmaxf(mx, smx[tid + 64 * k]);
        }
        float cnt = fmaxf((float)(end - start), 1.0f);
        float mean = (float)(sum / cnt);
        float var  = (float)(sum2 / cnt) - mean * mean;
        float stdv = sqrtf(fmaxf(var, 0.f) + 1e-5f);
        g_segfeat[s * 256 + c]        = mean;
        g_segfeat[s * 256 + 64 + c]   = mn;
        g_segfeat[s * 256 + 128 + c]  = mx;
        g_segfeat[s * 256 + 192 + c]  = stdv;
    }
}

// ---------------- projection: [S,256] @ Wp[256,64] + bp ----------------
__global__ void k_proj(const float* __restrict__ Wp, const float* __restrict__ bp) {
    int idx = blockIdx.x * blockDim.x + threadIdx.x;
    if (idx >= S_SEG * 64) return;
    int s = idx >> 6, c = idx & 63;
    float acc = bp[c];
    const float* f = &g_segfeat[s * 256];
    #pragma unroll 8
    for (int k = 0; k < 256; k++)
        acc = fmaf(f[k], Wp[k * 64 + c], acc);
    g_proj[idx] = acc;
}

// ---------------- pack: out[b,c,j,i] = proj[offs[b] + i*14+j, c] (masked) ----------------
__global__ void k_pack(const int* __restrict__ num_sp, float* __restrict__ out) {
    int idx = blockIdx.x * blockDim.x + threadIdx.x;
    if (idx >= B_IMG * 64 * 196) return;
    int b   = idx / (64 * 196);
    int rem = idx - b * (64 * 196);
    int c   = rem / 196;
    int ji  = rem - c * 196;
    int j = ji / 14, ii = ji - j * 14;
    int p = ii * 14 + j;
    int ns = num_sp[b];
    int off = 0;
    for (int q = 0; q < b; q++) off += num_sp[q];
    float v = 0.f;
    if (p < ns) {
        int row = off + p;
        if (row > S_SEG - 1) row = S_SEG - 1;
        v = g_proj[row * 64 + c];
    }
    out[idx] = v;
}

// ---------------- host orchestration ----------------
template<int FI, int FO, bool BN>
static void run_layer(const float* xin, const float* W,
                      const float* g, const float* be, int n) {
    constexpr int NPB = 256 / FO;
    k_gemm<FI, FO, BN><<<(n + NPB - 1) / NPB, 256>>>(xin, W, n);
    if (FO >= 32) k_agg_grp<FO><<<1184, 256>>>(n);
    else          k_agg_tpn<FO><<<592, 256>>>(n);
    k_bnfin<<<1, 64>>>(g, be, n, FO);
}

extern "C" void kernel_launch(void* const* d_in, const int* in_sizes, int n_in,
                              void* d_out, int out_size) {
    const float* x        = (const float*)d_in[0];
    const int*   ei       = (const int*)d_in[1];
    const int*   batchidx = (const int*)d_in[2];
    const int*   num_sp   = (const int*)d_in[3];
    const int n = in_sizes[2];
    const int e = in_sizes[1] / 2;
    const int* src = ei;
    const int* dst = ei + e;

    const float* W[5], *g[5], *be[5];
    for (int i = 0; i < 5; i++) {
        W[i]  = (const float*)d_in[4 + 4 * i];
        g[i]  = (const float*)d_in[6 + 4 * i];
        be[i] = (const float*)d_in[7 + 4 * i];
    }
    const float* Wp = (const float*)d_in[24];
    const float* bp = (const float*)d_in[25];
    float* out = (float*)d_out;

    // degrees + CSR build (once per launch; reused by all 5 layers)
    k_zero_nodes<<<(n + 255) / 256, 256>>>(n);
    k_deg_count<<<(e + 255) / 256, 256>>>(dst, e);
    k_deg_fin<<<(n + 255) / 256, 256>>>(n);
    int nb = (n + SCAN_CHUNK - 1) / SCAN_CHUNK;
    k_scan1<<<nb, 256>>>(n);
    k_scan2<<<1, 512>>>(nb);
    k_scan3<<<nb, 256>>>(n, e);
    k_fill<<<(e + 255) / 256, 256>>>(src, dst, e);

    // 5 GCN layers (BN folded into affine applied on next read; stats fused in agg)
    run_layer<24,  8, false>(x,       W[0], g[0], be[0], n);
    run_layer< 8, 16, true >(nullptr, W[1], g[1], be[1], n);
    run_layer<16, 32, true >(nullptr, W[2], g[2], be[2], n);
    run_layer<32, 64, true >(nullptr, W[3], g[3], be[3], n);
    run_layer<64, 64, true >(nullptr, W[4], g[4], be[4], n);

    // segment aggregation (applies layer-5 BN affine, no ReLU)
    k_segagg<<<S_SEG, 256>>>(batchidx, n);
    k_proj<<<(S_SEG * 64 + 255) / 256, 256>>>(Wp, bp);
    k_pack<<<(B_IMG * 64 * 196 + 255) / 256, 256>>>(num_sp, out);
}

// round 5
// speedup vs baseline: 1.3984x; 1.3984x over previous
#include <cuda_runtime.h>
#include <math.h>

// Problem constants (fixed shapes per reference)
#define NN 400000
#define EE 3200000
#define S_SEG 1200
#define B_IMG 8

// ---------------- device scratch (static globals; no allocation) ----------------
__device__ __align__(16) float  g_bufA[(size_t)NN * 64];   // h_i (post-GEMM, pre-BN)
__device__ __align__(16) float  g_bufB[(size_t)NN * 64];   // z_i (aggregated) / L1 gemm out
__device__ float  g_dis[NN];                 // rsqrt(deg)
__device__ int    g_degi[NN];
__device__ int    g_rowptr[NN + 1];
__device__ int    g_cursor[NN];
__device__ int    g_csr[EE];                 // src indices grouped by dst
__device__ int    g_bsums[512];
__device__ double g_stats[128];              // per-channel sum / sumsq
__device__ float  g_scale[64];
__device__ float  g_shift[64];
__device__ float  g_segfeat[S_SEG * 256];
__device__ float  g_proj[S_SEG * 64];

// ---------------- degree / CSR build ----------------
__global__ void k_zero_nodes(int n) {
    int i = blockIdx.x * blockDim.x + threadIdx.x;
    if (i < n) { g_degi[i] = 0; g_cursor[i] = 0; }
    if (blockIdx.x == 0 && threadIdx.x < 128) g_stats[threadIdx.x] = 0.0;
}
__global__ void k_deg_count(const int* __restrict__ dst, int e) {
    int i = blockIdx.x * blockDim.x + threadIdx.x;
    if (i < e) atomicAdd(&g_degi[dst[i]], 1);
}
__global__ void k_deg_fin(int n) {
    int i = blockIdx.x * blockDim.x + threadIdx.x;
    if (i < n) g_dis[i] = rsqrtf((float)(g_degi[i] + 1));  // +1 self loop
}

#define SCAN_CHUNK 1024
__global__ void k_scan1(int n) {
    __shared__ int sh[256];
    int base = blockIdx.x * SCAN_CHUNK;
    int t = threadIdx.x;
    int v[4]; int loc = 0;
    #pragma unroll
    for (int k = 0; k < 4; k++) {
        int i = base + t * 4 + k;
        v[k] = (i < n) ? g_degi[i] : 0;
        loc += v[k];
    }
    sh[t] = loc;
    __syncthreads();
    for (int off = 1; off < 256; off <<= 1) {
        int x = sh[t];
        int y = (t >= off) ? sh[t - off] : 0;
        __syncthreads();
        sh[t] = x + y;
        __syncthreads();
    }
    int excl = (t == 0) ? 0 : sh[t - 1];
    if (t == 255) g_bsums[blockIdx.x] = sh[255];
    int run = excl;
    #pragma unroll
    for (int k = 0; k < 4; k++) {
        int i = base + t * 4 + k;
        if (i < n) g_rowptr[i] = run;
        run += v[k];
    }
}
__global__ void k_scan2(int nb) {
    __shared__ int sh[512];
    int t = threadIdx.x;
    sh[t] = (t < nb) ? g_bsums[t] : 0;
    __syncthreads();
    for (int off = 1; off < 512; off <<= 1) {
        int x = sh[t];
        int y = (t >= off) ? sh[t - off] : 0;
        __syncthreads();
        sh[t] = x + y;
        __syncthreads();
    }
    if (t < nb) g_bsums[t] = (t == 0) ? 0 : sh[t - 1];
}
__global__ void k_scan3(int n, int e) {
    int base = blockIdx.x * SCAN_CHUNK;
    int add = g_bsums[blockIdx.x];
    int t = threadIdx.x;
    #pragma unroll
    for (int k = 0; k < 4; k++) {
        int i = base + t * 4 + k;
        if (i < n) g_rowptr[i] += add;
    }
    if (blockIdx.x == 0 && t == 0) g_rowptr[n] = e;
}
__global__ void k_fill(const int* __restrict__ src, const int* __restrict__ dst, int e) {
    int i = blockIdx.x * blockDim.x + threadIdx.x;
    if (i < e) {
        int d = dst[i];
        int p = atomicAdd(&g_cursor[d], 1);
        g_csr[g_rowptr[d] + p] = src[i];
    }
}

// ---------------- L1 GEMM: bufB = (x @ W1) * dis[node] ----------------
__global__ void k_gemm1(const float* __restrict__ xin, const float* __restrict__ W, int n) {
    constexpr int FI = 24, FO = 8, NPB = 32;
    __shared__ float Ws[FI * FO];
    __shared__ float xs[NPB * FI];
    int tid = threadIdx.x;
    for (int i = tid; i < FI * FO; i += 256) Ws[i] = W[i];
    int base = blockIdx.x * NPB;
    for (int i = tid; i < NPB * FI; i += 256) {
        int ln = i / FI, k = i - ln * FI;
        int node = base + ln;
        xs[i] = (node < n) ? xin[(size_t)node * FI + k] : 0.f;
    }
    __syncthreads();
    int c = tid % FO, ln = tid / FO;
    int node = base + ln;
    if (node < n) {
        float acc = 0.f;
        #pragma unroll
        for (int k = 0; k < FI; k++)
            acc = fmaf(xs[ln * FI + k], Ws[k * FO + c], acc);
        g_bufB[(size_t)node * FO + c] = acc * g_dis[node];
    }
}

// ---------------- L1 post-agg (dim 8) + fused BN stats ----------------
__global__ void k_agg_post8(int n) {
    __shared__ float ss[8], ss2[8];
    int tid = threadIdx.x;
    if (tid < 8) { ss[tid] = 0.f; ss2[tid] = 0.f; }
    __syncthreads();
    const float4* in = (const float4*)g_bufB;
    float4* outb = (float4*)g_bufA;
    float ls[8], ls2[8];
    #pragma unroll
    for (int c = 0; c < 8; c++) { ls[c] = 0.f; ls2[c] = 0.f; }
    for (int d = blockIdx.x * 256 + tid; d < n; d += gridDim.x * 256) {
        float4 a0 = in[(size_t)d * 2];
        float4 a1 = in[(size_t)d * 2 + 1];
        int beg = g_rowptr[d], end = g_rowptr[d + 1];
        for (int j = beg; j < end; j++) {
            int s = g_csr[j];
            float4 v0 = in[(size_t)s * 2];
            float4 v1 = in[(size_t)s * 2 + 1];
            a0.x += v0.x; a0.y += v0.y; a0.z += v0.z; a0.w += v0.w;
            a1.x += v1.x; a1.y += v1.y; a1.z += v1.z; a1.w += v1.w;
        }
        float dd = g_dis[d];
        a0.x *= dd; a0.y *= dd; a0.z *= dd; a0.w *= dd;
        a1.x *= dd; a1.y *= dd; a1.z *= dd; a1.w *= dd;
        outb[(size_t)d * 2] = a0;
        outb[(size_t)d * 2 + 1] = a1;
        ls[0] += a0.x; ls2[0] += a0.x * a0.x;
        ls[1] += a0.y; ls2[1] += a0.y * a0.y;
        ls[2] += a0.z; ls2[2] += a0.z * a0.z;
        ls[3] += a0.w; ls2[3] += a0.w * a0.w;
        ls[4] += a1.x; ls2[4] += a1.x * a1.x;
        ls[5] += a1.y; ls2[5] += a1.y * a1.y;
        ls[6] += a1.z; ls2[6] += a1.z * a1.z;
        ls[7] += a1.w; ls2[7] += a1.w * a1.w;
    }
    #pragma unroll
    for (int c = 0; c < 8; c++) {
        atomicAdd(&ss[c], ls[c]);
        atomicAdd(&ss2[c], ls2[c]);
    }
    __syncthreads();
    if (tid < 8) {
        atomicAdd(&g_stats[tid], (double)ss[tid]);
        atomicAdd(&g_stats[64 + tid], (double)ss2[tid]);
    }
}

// ---------------- pre-agg (thread per node, FI=8/16): z = agg(relu(affine(h))·dis) ----------------
template<int FI>
__global__ void k_agg_pre_tpn(int n) {
    constexpr int NF4 = FI / 4;
    const float4* in = (const float4*)g_bufA;
    float4* outb = (float4*)g_bufB;
    float4 sc4[NF4], sh4[NF4];
    #pragma unroll
    for (int f = 0; f < NF4; f++) {
        sc4[f] = ((const float4*)g_scale)[f];
        sh4[f] = ((const float4*)g_shift)[f];
    }
    for (int d = blockIdx.x * blockDim.x + threadIdx.x; d < n; d += gridDim.x * blockDim.x) {
        float dd = g_dis[d];
        float4 acc[NF4];
        #pragma unroll
        for (int f = 0; f < NF4; f++) {
            float4 v = in[(size_t)d * NF4 + f];
            acc[f].x = fmaxf(fmaf(sc4[f].x, v.x, sh4[f].x), 0.f) * dd;
            acc[f].y = fmaxf(fmaf(sc4[f].y, v.y, sh4[f].y), 0.f) * dd;
            acc[f].z = fmaxf(fmaf(sc4[f].z, v.z, sh4[f].z), 0.f) * dd;
            acc[f].w = fmaxf(fmaf(sc4[f].w, v.w, sh4[f].w), 0.f) * dd;
        }
        int beg = g_rowptr[d], end = g_rowptr[d + 1];
        for (int j = beg; j < end; j++) {
            int s = g_csr[j];
            float ds = g_dis[s];
            #pragma unroll
            for (int f = 0; f < NF4; f++) {
                float4 v = in[(size_t)s * NF4 + f];
                acc[f].x += fmaxf(fmaf(sc4[f].x, v.x, sh4[f].x), 0.f) * ds;
                acc[f].y += fmaxf(fmaf(sc4[f].y, v.y, sh4[f].y), 0.f) * ds;
                acc[f].z += fmaxf(fmaf(sc4[f].z, v.z, sh4[f].z), 0.f) * ds;
                acc[f].w += fmaxf(fmaf(sc4[f].w, v.w, sh4[f].w), 0.f) * ds;
            }
        }
        #pragma unroll
        for (int f = 0; f < NF4; f++) {
            acc[f].x *= dd; acc[f].y *= dd; acc[f].z *= dd; acc[f].w *= dd;
            outb[(size_t)d * NF4 + f] = acc[f];
        }
    }
}

// ---------------- pre-agg (TPN lanes per node, FI=32/64) ----------------
template<int FI>
__global__ void k_agg_pre_grp(int n) {
    constexpr int TPN = FI / 4;
    constexpr int NPB = 256 / TPN;
    int tid = threadIdx.x;
    int grp = tid / TPN, lane = tid % TPN;
    float4 sc = ((const float4*)g_scale)[lane];
    float4 sh = ((const float4*)g_shift)[lane];
    const float4* in = (const float4*)g_bufA;
    float4* outb = (float4*)g_bufB;
    for (int d = blockIdx.x * NPB + grp; d < n; d += gridDim.x * NPB) {
        float dd = g_dis[d];
        float4 v = in[(size_t)d * TPN + lane];
        float4 acc;
        acc.x = fmaxf(fmaf(sc.x, v.x, sh.x), 0.f) * dd;
        acc.y = fmaxf(fmaf(sc.y, v.y, sh.y), 0.f) * dd;
        acc.z = fmaxf(fmaf(sc.z, v.z, sh.z), 0.f) * dd;
        acc.w = fmaxf(fmaf(sc.w, v.w, sh.w), 0.f) * dd;
        int beg = g_rowptr[d], end = g_rowptr[d + 1];
        for (int j = beg; j < end; j++) {
            int s = g_csr[j];
            float ds = g_dis[s];
            v = in[(size_t)s * TPN + lane];
            acc.x += fmaxf(fmaf(sc.x, v.x, sh.x), 0.f) * ds;
            acc.y += fmaxf(fmaf(sc.y, v.y, sh.y), 0.f) * ds;
            acc.z += fmaxf(fmaf(sc.z, v.z, sh.z), 0.f) * ds;
            acc.w += fmaxf(fmaf(sc.w, v.w, sh.w), 0.f) * ds;
        }
        acc.x *= dd; acc.y *= dd; acc.z *= dd; acc.w *= dd;
        outb[(size_t)d * TPN + lane] = acc;
    }
}

// ---------------- GEMM with fused BN stats: bufA = bufB @ W ----------------
template<int FI, int FO>
__global__ void k_gemm_stats(const float* __restrict__ W, int n) {
    constexpr int NPB = 256 / FO;
    __shared__ float xs[NPB * FI];
    int tid = threadIdx.x;
    int c = tid % FO, ln = tid / FO;
    float w[FI];
    #pragma unroll
    for (int k = 0; k < FI; k++) w[k] = W[k * FO + c];
    float s1 = 0.f, s2 = 0.f;
    for (int base = blockIdx.x * NPB; base < n; base += gridDim.x * NPB) {
        __syncthreads();
        for (int i = tid; i < NPB * FI; i += 256) {
            int node = base + i / FI;
            xs[i] = (node < n) ? g_bufB[(size_t)node * FI + (i % FI)] : 0.f;
        }
        __syncthreads();
        int node = base + ln;
        if (node < n) {
            float acc = 0.f;
            #pragma unroll
            for (int k = 0; k < FI; k++)
                acc = fmaf(xs[ln * FI + k], w[k], acc);
            g_bufA[(size_t)node * FO + c] = acc;
            s1 += acc; s2 += acc * acc;
        }
    }
    __shared__ float r1[256], r2[256];
    r1[tid] = s1; r2[tid] = s2;
    __syncthreads();
    if (ln == 0) {
        #pragma unroll
        for (int k = 1; k < NPB; k++) { s1 += r1[k * FO + c]; s2 += r2[k * FO + c]; }
        atomicAdd(&g_stats[c], (double)s1);
        atomicAdd(&g_stats[64 + c], (double)s2);
    }
}

// scale = g*rsqrt(var+eps); shift = be - scale*mean (bias b cancels); zero stats
__global__ void k_bnfin(const float* __restrict__ g, const float* __restrict__ be,
                        int n, int fo) {
    int c = threadIdx.x;
    if (c >= 64) return;
    double s  = g_stats[c];
    double s2 = g_stats[64 + c];
    g_stats[c] = 0.0; g_stats[64 + c] = 0.0;
    if (c < fo) {
        double mean = s / n;
        double var  = s2 / n - mean * mean;
        float rs = rsqrtf((float)var + 1e-5f);
        float sc = g[c] * rs;
        g_scale[c] = sc;
        g_shift[c] = be[c] - sc * (float)mean;
    }
}

// ---------------- segment multi-aggregation (batch_idx sorted) ----------------
__global__ void k_segagg(const int* __restrict__ bidx, int n) {
    int s = blockIdx.x;
    int tid = threadIdx.x;
    int c = tid & 63, rr = tid >> 6;
    int lo = 0, hi = n;
    while (lo < hi) { int m = (lo + hi) >> 1; if (bidx[m] < s) lo = m + 1; else hi = m; }
    int start = lo;
    hi = n;
    while (lo < hi) { int m = (lo + hi) >> 1; if (bidx[m] < s + 1) lo = m + 1; else hi = m; }
    int end = lo;
    float sc = g_scale[c], sh = g_shift[c];
    double sum = 0.0, sum2 = 0.0;
    float mn = INFINITY, mx = -INFINITY;
    for (int r = start + rr; r < end; r += 4) {
        float v = fmaf(sc, g_bufA[(size_t)r * 64 + c], sh);
        sum += v; sum2 += (double)v * v;
        mn = fminf(mn, v); mx = fmaxf(mx, v);
    }
    __shared__ double s1[256], s2[256];
    __shared__ float smn[256], smx[256];
    s1[tid] = sum; s2[tid] = sum2; smn[tid] = mn; smx[tid] = mx;
    __syncthreads();
    if (rr == 0) {
        #pragma unroll
        for (int k = 1; k < 4; k++) {
            sum += s1[tid + 64 * k]; sum2 += s2[tid + 64 * k];
            mn = fminf(mn, smn[tid + 64 * k]); mx = fmaxf(mx, smx[tid + 64 * k]);
        }
        float cnt = fmaxf((float)(end - start), 1.0f);
        float mean = (float)(sum / cnt);
        float var  = (float)(sum2 / cnt) - mean * mean;
        float stdv = sqrtf(fmaxf(var, 0.f) + 1e-5f);
        g_segfeat[s * 256 + c]        = mean;
        g_segfeat[s * 256 + 64 + c]   = mn;
        g_segfeat[s * 256 + 128 + c]  = mx;
        g_segfeat[s * 256 + 192 + c]  = stdv;
    }
}

// ---------------- projection: [S,256] @ Wp[256,64] + bp ----------------
__global__ void k_proj(const float* __restrict__ Wp, const float* __restrict__ bp) {
    int idx = blockIdx.x * blockDim.x + threadIdx.x;
    if (idx >= S_SEG * 64) return;
    int s = idx >> 6, c = idx & 63;
    float acc = bp[c];
    const float* f = &g_segfeat[s * 256];
    #pragma unroll 8
    for (int k = 0; k < 256; k++)
        acc = fmaf(f[k], Wp[k * 64 + c], acc);
    g_proj[idx] = acc;
}

// ---------------- pack: out[b,c,j,i] = proj[offs[b] + i*14+j, c] (masked) ----------------
__global__ void k_pack(const int* __restrict__ num_sp, float* __restrict__ out) {
    int idx = blockIdx.x * blockDim.x + threadIdx.x;
    if (idx >= B_IMG * 64 * 196) return;
    int b   = idx / (64 * 196);
    int rem = idx - b * (64 * 196);
    int c   = rem / 196;
    int ji  = rem - c * 196;
    int j = ji / 14, ii = ji - j * 14;
    int p = ii * 14 + j;
    int ns = num_sp[b];
    int off = 0;
    for (int q = 0; q < b; q++) off += num_sp[q];
    float v = 0.f;
    if (p < ns) {
        int row = off + p;
        if (row > S_SEG - 1) row = S_SEG - 1;
        v = g_proj[row * 64 + c];
    }
    out[idx] = v;
}

// ---------------- host orchestration ----------------
extern "C" void kernel_launch(void* const* d_in, const int* in_sizes, int n_in,
                              void* d_out, int out_size) {
    const float* x        = (const float*)d_in[0];
    const int*   ei       = (const int*)d_in[1];
    const int*   batchidx = (const int*)d_in[2];
    const int*   num_sp   = (const int*)d_in[3];
    const int n = in_sizes[2];
    const int e = in_sizes[1] / 2;
    const int* src = ei;
    const int* dst = ei + e;

    const float* W[5], *g[5], *be[5];
    for (int i = 0; i < 5; i++) {
        W[i]  = (const float*)d_in[4 + 4 * i];
        g[i]  = (const float*)d_in[6 + 4 * i];
        be[i] = (const float*)d_in[7 + 4 * i];
    }
    const float* Wp = (const float*)d_in[24];
    const float* bp = (const float*)d_in[25];
    float* out = (float*)d_out;

    // degrees + CSR build (once per launch)
    k_zero_nodes<<<(n + 255) / 256, 256>>>(n);
    k_deg_count<<<(e + 255) / 256, 256>>>(dst, e);
    k_deg_fin<<<(n + 255) / 256, 256>>>(n);
    int nb = (n + SCAN_CHUNK - 1) / SCAN_CHUNK;
    k_scan1<<<nb, 256>>>(n);
    k_scan2<<<1, 512>>>(nb);
    k_scan3<<<nb, 256>>>(n, e);
    k_fill<<<(e + 255) / 256, 256>>>(src, dst, e);

    const int AB = 1184;   // agg grid
    const int GB = 1480;   // gemm grid

    // L1: GEMM (24->8) then post-agg in dim 8 (stats fused in agg)
    k_gemm1<<<(n + 31) / 32, 256>>>(x, W[0], n);
    k_agg_post8<<<AB, 256>>>(n);
    k_bnfin<<<1, 64>>>(g[0], be[0], n, 8);

    // L2: pre-agg dim 8, GEMM 8->16 (stats fused)
    k_agg_pre_tpn<8><<<AB, 256>>>(n);
    k_gemm_stats<8, 16><<<GB, 256>>>(W[1], n);
    k_bnfin<<<1, 64>>>(g[1], be[1], n, 16);

    // L3: pre-agg dim 16, GEMM 16->32
    k_agg_pre_tpn<16><<<AB, 256>>>(n);
    k_gemm_stats<16, 32><<<GB, 256>>>(W[2], n);
    k_bnfin<<<1, 64>>>(g[2], be[2], n, 32);

    // L4: pre-agg dim 32, GEMM 32->64
    k_agg_pre_grp<32><<<AB, 256>>>(n);
    k_gemm_stats<32, 64><<<GB, 256>>>(W[3], n);
    k_bnfin<<<1, 64>>>(g[3], be[3], n, 64);

    // L5: pre-agg dim 64, GEMM 64->64
    k_agg_pre_grp<64><<<AB, 256>>>(n);
    k_gemm_stats<64, 64><<<GB, 256>>>(W[4], n);
    k_bnfin<<<1, 64>>>(g[4], be[4], n, 64);

    // segment aggregation (applies L5 BN affine, no ReLU)
    k_segagg<<<S_SEG, 256>>>(batchidx, n);
    k_proj<<<(S_SEG * 64 + 255) / 256, 256>>>(Wp, bp);
    k_pack<<<(B_IMG * 64 * 196 + 255) / 256, 256>>>(num_sp, out);
}

// round 7
// speedup vs baseline: 1.4920x; 1.0669x over previous
#include <cuda_runtime.h>
#include <math.h>

// Problem constants (fixed shapes per reference)
#define NN 400000
#define EE 3200000
#define S_SEG 1200
#define B_IMG 8

// ---------------- device scratch (static globals; no allocation) ----------------
__device__ __align__(16) float  g_bufA[(size_t)NN * 64];
__device__ __align__(16) float  g_bufB[(size_t)NN * 64];
__device__ float  g_dis[NN];                 // rsqrt(deg)
__device__ int    g_degi[NN];
__device__ int    g_rowptr[NN + 1];
__device__ int    g_cursor[NN];
__device__ int    g_csr[EE];                 // src indices grouped by dst
__device__ int    g_bsums[512];
__device__ double g_stats[128];              // per-channel sum / sumsq
__device__ float  g_scale[64];
__device__ float  g_shift[64];
__device__ float  g_segfeat[S_SEG * 256];
__device__ float  g_proj[S_SEG * 64];

// ---------------- packed f32x2 helpers (sm_103a) ----------------
__device__ __forceinline__ unsigned long long f2add(unsigned long long a, unsigned long long b) {
    unsigned long long r;
    asm("add.rn.f32x2 %0, %1, %2;" : "=l"(r) : "l"(a), "l"(b));
    return r;
}
__device__ __forceinline__ unsigned long long f2mul(unsigned long long a, unsigned long long b) {
    unsigned long long r;
    asm("mul.rn.f32x2 %0, %1, %2;" : "=l"(r) : "l"(a), "l"(b));
    return r;
}
__device__ __forceinline__ unsigned long long f2pack(float x) {
    unsigned long long r;
    asm("mov.b64 %0, {%1, %1};" : "=l"(r) : "f"(x));
    return r;
}
__device__ __forceinline__ void f2unpack(unsigned long long v, float& lo, float& hi) {
    asm("mov.b64 {%0, %1}, %2;" : "=f"(lo), "=f"(hi) : "l"(v));
}

// ---------------- degree / CSR build ----------------
__global__ void k_zero_nodes(int n) {
    int i = blockIdx.x * blockDim.x + threadIdx.x;
    if (i < n) { g_degi[i] = 0; g_cursor[i] = 0; }
    if (blockIdx.x == 0 && threadIdx.x < 128) g_stats[threadIdx.x] = 0.0;
}
__global__ void k_deg_count(const int* __restrict__ dst, int e) {
    int i = blockIdx.x * blockDim.x + threadIdx.x;
    if (i < e) atomicAdd(&g_degi[dst[i]], 1);
}
__global__ void k_deg_fin(int n) {
    int i = blockIdx.x * blockDim.x + threadIdx.x;
    if (i < n) g_dis[i] = rsqrtf((float)(g_degi[i] + 1));  // +1 self loop
}

#define SCAN_CHUNK 1024
__global__ void k_scan1(int n) {
    __shared__ int sh[256];
    int base = blockIdx.x * SCAN_CHUNK;
    int t = threadIdx.x;
    int v[4]; int loc = 0;
    #pragma unroll
    for (int k = 0; k < 4; k++) {
        int i = base + t * 4 + k;
        v[k] = (i < n) ? g_degi[i] : 0;
        loc += v[k];
    }
    sh[t] = loc;
    __syncthreads();
    for (int off = 1; off < 256; off <<= 1) {
        int x = sh[t];
        int y = (t >= off) ? sh[t - off] : 0;
        __syncthreads();
        sh[t] = x + y;
        __syncthreads();
    }
    int excl = (t == 0) ? 0 : sh[t - 1];
    if (t == 255) g_bsums[blockIdx.x] = sh[255];
    int run = excl;
    #pragma unroll
    for (int k = 0; k < 4; k++) {
        int i = base + t * 4 + k;
        if (i < n) g_rowptr[i] = run;
        run += v[k];
    }
}
__global__ void k_scan2(int nb) {
    __shared__ int sh[512];
    int t = threadIdx.x;
    sh[t] = (t < nb) ? g_bsums[t] : 0;
    __syncthreads();
    for (int off = 1; off < 512; off <<= 1) {
        int x = sh[t];
        int y = (t >= off) ? sh[t - off] : 0;
        __syncthreads();
        sh[t] = x + y;
        __syncthreads();
    }
    if (t < nb) g_bsums[t] = (t == 0) ? 0 : sh[t - 1];
}
__global__ void k_scan3(int n, int e) {
    int base = blockIdx.x * SCAN_CHUNK;
    int add = g_bsums[blockIdx.x];
    int t = threadIdx.x;
    #pragma unroll
    for (int k = 0; k < 4; k++) {
        int i = base + t * 4 + k;
        if (i < n) g_rowptr[i] += add;
    }
    if (blockIdx.x == 0 && t == 0) g_rowptr[n] = e;
}
__global__ void k_fill(const int* __restrict__ src, const int* __restrict__ dst, int e) {
    int i = blockIdx.x * blockDim.x + threadIdx.x;
    if (i < e) {
        int d = dst[i];
        int p = atomicAdd(&g_cursor[d], 1);
        g_csr[g_rowptr[d] + p] = src[i];
    }
}

// ---------------- L1 GEMM: bufB = (x @ W1) * dis[node]  (u for layer 1) ----------------
__global__ void k_gemm1(const float* __restrict__ xin, const float* __restrict__ W, int n) {
    constexpr int FI = 24, FO = 8, NPB = 32;
    __shared__ float Ws[FI * FO];
    __shared__ float xs[NPB * FI];
    int tid = threadIdx.x;
    for (int i = tid; i < FI * FO; i += 256) Ws[i] = W[i];
    int base = blockIdx.x * NPB;
    for (int i = tid; i < NPB * FI; i += 256) {
        int ln = i / FI, k = i - ln * FI;
        int node = base + ln;
        xs[i] = (node < n) ? xin[(size_t)node * FI + k] : 0.f;
    }
    __syncthreads();
    int c = tid % FO, ln = tid / FO;
    int node = base + ln;
    if (node < n) {
        float acc = 0.f;
        #pragma unroll
        for (int k = 0; k < FI; k++)
            acc = fmaf(xs[ln * FI + k], Ws[k * FO + c], acc);
        g_bufB[(size_t)node * FO + c] = acc * g_dis[node];
    }
}

// ---------------- prep: u = relu(affine(h)) * dis  (streaming, per-node) ----------------
template<int D, bool IN_A>
__global__ void k_prep(int n) {
    constexpr int NC = D / 4;
    const float4* in = (const float4*)(IN_A ? g_bufA : g_bufB);
    float4* out      = (float4*)(IN_A ? g_bufB : g_bufA);
    long long tot = (long long)n * NC;
    for (long long idx = (long long)blockIdx.x * blockDim.x + threadIdx.x;
         idx < tot; idx += (long long)gridDim.x * blockDim.x) {
        int node = (int)(idx / NC);
        int f = (int)(idx - (long long)node * NC);
        float dd = g_dis[node];
        float4 sc = ((const float4*)g_scale)[f];
        float4 sh = ((const float4*)g_shift)[f];
        float4 v = in[idx];
        float4 o;
        o.x = fmaxf(fmaf(sc.x, v.x, sh.x), 0.f) * dd;
        o.y = fmaxf(fmaf(sc.y, v.y, sh.y), 0.f) * dd;
        o.z = fmaxf(fmaf(sc.z, v.z, sh.z), 0.f) * dd;
        o.w = fmaxf(fmaf(sc.w, v.w, sh.w), 0.f) * dd;
        out[idx] = o;
    }
}

// ---------------- pure-sum gather, thread-per-node (D=8/16), packed adds ----------------
// STATS=true (L1 only, D=8): fused BN stats of output z.
template<int D, bool IN_A, bool STATS>
__global__ void k_agg_tpn(int n) {
    constexpr int NC = D / 4;   // 16B chunks per node
    __shared__ float ss[8], ss2[8];
    int tid = threadIdx.x;
    if (STATS) {
        if (tid < 8) { ss[tid] = 0.f; ss2[tid] = 0.f; }
        __syncthreads();
    }
    const ulonglong2* in = (const ulonglong2*)(IN_A ? g_bufA : g_bufB);
    ulonglong2* out      = (ulonglong2*)(IN_A ? g_bufB : g_bufA);
    float ls[8], ls2[8];
    if (STATS) {
        #pragma unroll
        for (int c = 0; c < 8; c++) { ls[c] = 0.f; ls2[c] = 0.f; }
    }
    for (int d = blockIdx.x * blockDim.x + threadIdx.x; d < n; d += gridDim.x * blockDim.x) {
        ulonglong2 acc[NC];
        #pragma unroll
        for (int f = 0; f < NC; f++) acc[f] = in[(size_t)d * NC + f];   // self term u[d]
        int beg = g_rowptr[d], end = g_rowptr[d + 1];
        #pragma unroll 2
        for (int j = beg; j < end; j++) {
            int s = g_csr[j];
            #pragma unroll
            for (int f = 0; f < NC; f++) {
                ulonglong2 v = in[(size_t)s * NC + f];
                acc[f].x = f2add(acc[f].x, v.x);
                acc[f].y = f2add(acc[f].y, v.y);
            }
        }
        unsigned long long dd2 = f2pack(g_dis[d]);
        #pragma unroll
        for (int f = 0; f < NC; f++) {
            acc[f].x = f2mul(acc[f].x, dd2);
            acc[f].y = f2mul(acc[f].y, dd2);
            out[(size_t)d * NC + f] = acc[f];
            if (STATS) {
                float a, b;
                f2unpack(acc[f].x, a, b);
                ls[f * 4 + 0] += a; ls2[f * 4 + 0] += a * a;
                ls[f * 4 + 1] += b; ls2[f * 4 + 1] += b * b;
                f2unpack(acc[f].y, a, b);
                ls[f * 4 + 2] += a; ls2[f * 4 + 2] += a * a;
                ls[f * 4 + 3] += b; ls2[f * 4 + 3] += b * b;
            }
        }
    }
    if (STATS) {
        #pragma unroll
        for (int c = 0; c < 8; c++) {
            atomicAdd(&ss[c], ls[c]);
            atomicAdd(&ss2[c], ls2[c]);
        }
        __syncthreads();
        if (tid < 8) {
            atomicAdd(&g_stats[tid], (double)ss[tid]);
            atomicAdd(&g_stats[64 + tid], (double)ss2[tid]);
        }
    }
}

// ---------------- pure-sum gather, group variant (D=32/64), packed adds ----------------
template<int D, bool IN_A>
__global__ void k_agg_grp(int n) {
    constexpr int TPN = D / 4;          // lanes per node (16B each)
    constexpr int NPB = 256 / TPN;
    int tid = threadIdx.x;
    int grp = tid / TPN, lane = tid % TPN;
    const ulonglong2* in = (const ulonglong2*)(IN_A ? g_bufA : g_bufB);
    ulonglong2* out      = (ulonglong2*)(IN_A ? g_bufB : g_bufA);
    for (int d = blockIdx.x * NPB + grp; d < n; d += gridDim.x * NPB) {
        ulonglong2 acc = in[(size_t)d * TPN + lane];   // self term
        int beg = g_rowptr[d], end = g_rowptr[d + 1];
        #pragma unroll 2
        for (int j = beg; j < end; j++) {
            int s = g_csr[j];
            ulonglong2 v = in[(size_t)s * TPN + lane];
            acc.x = f2add(acc.x, v.x);
            acc.y = f2add(acc.y, v.y);
        }
        unsigned long long dd2 = f2pack(g_dis[d]);
        acc.x = f2mul(acc.x, dd2);
        acc.y = f2mul(acc.y, dd2);
        out[(size_t)d * TPN + lane] = acc;
    }
}

// ---------------- GEMM with fused BN stats: h = z @ W ----------------
template<int FI, int FO, bool IN_A>
__global__ void k_gemm_stats(const float* __restrict__ W, int n) {
    constexpr int NPB = 256 / FO;
    __shared__ float xs[NPB * FI];
    const float* zin = IN_A ? g_bufA : g_bufB;
    float* hout      = IN_A ? g_bufB : g_bufA;
    int tid = threadIdx.x;
    int c = tid % FO, ln = tid / FO;
    float w[FI];
    #pragma unroll
    for (int k = 0; k < FI; k++) w[k] = W[k * FO + c];
    float s1 = 0.f, s2 = 0.f;
    for (int base = blockIdx.x * NPB; base < n; base += gridDim.x * NPB) {
        __syncthreads();
        for (int i = tid; i < NPB * FI; i += 256) {
            int node = base + i / FI;
            xs[i] = (node < n) ? zin[(size_t)node * FI + (i % FI)] : 0.f;
        }
        __syncthreads();
        int node = base + ln;
        if (node < n) {
            float acc = 0.f;
            #pragma unroll
            for (int k = 0; k < FI; k++)
                acc = fmaf(xs[ln * FI + k], w[k], acc);
            hout[(size_t)node * FO + c] = acc;
            s1 += acc; s2 += acc * acc;
        }
    }
    __shared__ float r1[256], r2[256];
    r1[tid] = s1; r2[tid] = s2;
    __syncthreads();
    if (ln == 0) {
        #pragma unroll
        for (int k = 1; k < NPB; k++) { s1 += r1[k * FO + c]; s2 += r2[k * FO + c]; }
        atomicAdd(&g_stats[c], (double)s1);
        atomicAdd(&g_stats[64 + c], (double)s2);
    }
}

// scale = g*rsqrt(var+eps); shift = be - scale*mean (bias b cancels); zero stats
__global__ void k_bnfin(const float* __restrict__ g, const float* __restrict__ be,
                        int n, int fo) {
    int c = threadIdx.x;
    if (c >= 64) return;
    double s  = g_stats[c];
    double s2 = g_stats[64 + c];
    g_stats[c] = 0.0; g_stats[64 + c] = 0.0;
    if (c < fo) {
        double mean = s / n;
        double var  = s2 / n - mean * mean;
        float rs = rsqrtf((float)var + 1e-5f);
        float sc = g[c] * rs;
        g_scale[c] = sc;
        g_shift[c] = be[c] - sc * (float)mean;
    }
}

// ---------------- segment multi-aggregation (batch_idx sorted) ----------------
__global__ void k_segagg(const int* __restrict__ bidx, int n) {
    int s = blockIdx.x;
    int tid = threadIdx.x;
    int c = tid & 63, rr = tid >> 6;
    int lo = 0, hi = n;
    while (lo < hi) { int m = (lo + hi) >> 1; if (bidx[m] < s) lo = m + 1; else hi = m; }
    int start = lo;
    hi = n;
    while (lo < hi) { int m = (lo + hi) >> 1; if (bidx[m] < s + 1) lo = m + 1; else hi = m; }
    int end = lo;
    float sc = g_scale[c], sh = g_shift[c];
    double sum = 0.0, sum2 = 0.0;
    float mn = INFINITY, mx = -INFINITY;
    for (int r = start + rr; r < end; r += 4) {
        float v = fmaf(sc, g_bufA[(size_t)r * 64 + c], sh);
        sum += v; sum2 += (double)v * v;
        mn = fminf(mn, v); mx = fmaxf(mx, v);
    }
    __shared__ double s1[256], s2[256];
    __shared__ float smn[256], smx[256];
    s1[tid] = sum; s2[tid] = sum2; smn[tid] = mn; smx[tid] = mx;
    __syncthreads();
    if (rr == 0) {
        #pragma unroll
        for (int k = 1; k < 4; k++) {
            sum += s1[tid + 64 * k]; sum2 += s2[tid + 64 * k];
            mn = fminf(mn, smn[tid + 64 * k]); mx = fmaxf(mx, smx[tid + 64 * k]);
        }
        float cnt = fmaxf((float)(end - start), 1.0f);
        float mean = (float)(sum / cnt);
        float var  = (float)(sum2 / cnt) - mean * mean;
        float stdv = sqrtf(fmaxf(var, 0.f) + 1e-5f);
        g_segfeat[s * 256 + c]        = mean;
        g_segfeat[s * 256 + 64 + c]   = mn;
        g_segfeat[s * 256 + 128 + c]  = mx;
        g_segfeat[s * 256 + 192 + c]  = stdv;
    }
}

// ---------------- projection: [S,256] @ Wp[256,64] + bp ----------------
__global__ void k_proj(const float* __restrict__ Wp, const float* __restrict__ bp) {
    int idx = blockIdx.x * blockDim.x + threadIdx.x;
    if (idx >= S_SEG * 64) return;
    int s = idx >> 6, c = idx & 63;
    float acc = bp[c];
    const float* f = &g_segfeat[s * 256];
    #pragma unroll 8
    for (int k = 0; k < 256; k++)
        acc = fmaf(f[k], Wp[k * 64 + c], acc);
    g_proj[idx] = acc;
}

// ---------------- pack: out[b,c,j,i] = proj[offs[b] + i*14+j, c] (masked) ----------------
__global__ void k_pack(const int* __restrict__ num_sp, float* __restrict__ out) {
    int idx = blockIdx.x * blockDim.x + threadIdx.x;
    if (idx >= B_IMG * 64 * 196) return;
    int b   = idx / (64 * 196);
    int rem = idx - b * (64 * 196);
    int c   = rem / 196;
    int ji  = rem - c * 196;
    int j = ji / 14, ii = ji - j * 14;
    int p = ii * 14 + j;
    int ns = num_sp[b];
    int off = 0;
    for (int q = 0; q < b; q++) off += num_sp[q];
    float v = 0.f;
    if (p < ns) {
        int row = off + p;
        if (row > S_SEG - 1) row = S_SEG - 1;
        v = g_proj[row * 64 + c];
    }
    out[idx] = v;
}

// ---------------- host orchestration ----------------
extern "C" void kernel_launch(void* const* d_in, const int* in_sizes, int n_in,
                              void* d_out, int out_size) {
    const float* x        = (const float*)d_in[0];
    const int*   ei       = (const int*)d_in[1];
    const int*   batchidx = (const int*)d_in[2];
    const int*   num_sp   = (const int*)d_in[3];
    const int n = in_sizes[2];
    const int e = in_sizes[1] / 2;
    const int* src = ei;
    const int* dst = ei + e;

    const float* W[5], *g[5], *be[5];
    for (int i = 0; i < 5; i++) {
        W[i]  = (const float*)d_in[4 + 4 * i];
        g[i]  = (const float*)d_in[6 + 4 * i];
        be[i] = (const float*)d_in[7 + 4 * i];
    }
    const float* Wp = (const float*)d_in[24];
    const float* bp = (const float*)d_in[25];
    float* out = (float*)d_out;

    // degrees + CSR build (once per launch)
    k_zero_nodes<<<(n + 255) / 256, 256>>>(n);
    k_deg_count<<<(e + 255) / 256, 256>>>(dst, e);
    k_deg_fin<<<(n + 255) / 256, 256>>>(n);
    int nb = (n + SCAN_CHUNK - 1) / SCAN_CHUNK;
    k_scan1<<<nb, 256>>>(n);
    k_scan2<<<1, 512>>>(nb);
    k_scan3<<<nb, 256>>>(n, e);
    k_fill<<<(e + 255) / 256, 256>>>(src, dst, e);

    const int AB = 1184;   // agg/prep grid
    const int GB = 1480;   // gemm grid

    // L1: GEMM (24->8, writes u=t*dis to B), pure-sum agg B->A (stats fused)
    k_gemm1<<<(n + 31) / 32, 256>>>(x, W[0], n);
    k_agg_tpn<8, false, true><<<AB, 256>>>(n);
    k_bnfin<<<1, 64>>>(g[0], be[0], n, 8);

    // L2: prep A->B (dim 8), agg B->A, gemm 8->16 A->B
    k_prep<8, true><<<AB, 256>>>(n);
    k_agg_tpn<8, false, false><<<AB, 256>>>(n);
    k_gemm_stats<8, 16, true><<<GB, 256>>>(W[1], n);
    k_bnfin<<<1, 64>>>(g[1], be[1], n, 16);

    // L3: prep B->A (dim 16), agg A->B, gemm 16->32 B->A
    k_prep<16, false><<<AB, 256>>>(n);
    k_agg_tpn<16, true, false><<<AB, 256>>>(n);
    k_gemm_stats<16, 32, false><<<GB, 256>>>(W[2], n);
    k_bnfin<<<1, 64>>>(g[2], be[2], n, 32);

    // L4: prep A->B (dim 32), agg B->A, gemm 32->64 A->B
    k_prep<32, true><<<AB, 256>>>(n);
    k_agg_grp<32, false><<<AB, 256>>>(n);
    k_gemm_stats<32, 64, true><<<GB, 256>>>(W[3], n);
    k_bnfin<<<1, 64>>>(g[3], be[3], n, 64);

    // L5: prep B->A (dim 64), agg A->B, gemm 64->64 B->A  (h5 in A)
    k_prep<64, false><<<AB, 256>>>(n);
    k_agg_grp<64, true><<<AB, 256>>>(n);
    k_gemm_stats<64, 64, false><<<GB, 256>>>(W[4], n);
    k_bnfin<<<1, 64>>>(g[4], be[4], n, 64);

    // segment aggregation (applies L5 BN affine, no ReLU)
    k_segagg<<<S_SEG, 256>>>(batchidx, n);
    k_proj<<<(S_SEG * 64 + 255) / 256, 256>>>(Wp, bp);
    k_pack<<<(B_IMG * 64 * 196 + 255) / 256, 256>>>(num_sp, out);
}

// round 9
// speedup vs baseline: 2.1000x; 1.4075x over previous
#include <cuda_runtime.h>
#include <math.h>

// Problem constants (fixed shapes per reference)
#define NN 400000
#define EE 3200000
#define S_SEG 1200
#define B_IMG 8

// ---------------- device scratch (static globals; no allocation) ----------------
__device__ __align__(16) float  g_bufA[(size_t)NN * 64];
__device__ __align__(16) float  g_bufB[(size_t)NN * 64];
__device__ float  g_dis[NN];                 // rsqrt(deg)
__device__ int    g_degi[NN];
__device__ int    g_rowptr[NN + 1];
__device__ int    g_cursor[NN];
__device__ int    g_csr[EE];                 // src indices grouped by dst
__device__ int    g_bsums[512];
__device__ double g_stats[128];              // per-channel sum / sumsq
__device__ float  g_scale[64];
__device__ float  g_shift[64];
__device__ float  g_segfeat[S_SEG * 256];
__device__ float  g_proj[S_SEG * 64];

// ---------------- packed f32x2 helpers (sm_103a) ----------------
__device__ __forceinline__ unsigned long long f2add(unsigned long long a, unsigned long long b) {
    unsigned long long r;
    asm("add.rn.f32x2 %0, %1, %2;" : "=l"(r) : "l"(a), "l"(b));
    return r;
}
__device__ __forceinline__ unsigned long long f2mul(unsigned long long a, unsigned long long b) {
    unsigned long long r;
    asm("mul.rn.f32x2 %0, %1, %2;" : "=l"(r) : "l"(a), "l"(b));
    return r;
}
__device__ __forceinline__ unsigned long long f2pack(float x) {
    unsigned long long r;
    asm("mov.b64 %0, {%1, %1};" : "=l"(r) : "f"(x));
    return r;
}
__device__ __forceinline__ void f2unpack(unsigned long long v, float& lo, float& hi) {
    asm("mov.b64 {%0, %1}, %2;" : "=f"(lo), "=f"(hi) : "l"(v));
}

// ---------------- degree / CSR build ----------------
__global__ void k_zero_nodes(int n) {
    int i = blockIdx.x * blockDim.x + threadIdx.x;
    if (i < n) { g_degi[i] = 0; g_cursor[i] = 0; }
    if (blockIdx.x == 0 && threadIdx.x < 128) g_stats[threadIdx.x] = 0.0;
}
__global__ void k_deg_count(const int* __restrict__ dst, int e) {
    int i = blockIdx.x * blockDim.x + threadIdx.x;
    if (i < e) atomicAdd(&g_degi[dst[i]], 1);
}

#define SCAN_CHUNK 1024
// scan of degi -> rowptr (block-local) + dis = rsqrt(deg+1) fused
__global__ void k_scan1(int n) {
    __shared__ int sh[256];
    int base = blockIdx.x * SCAN_CHUNK;
    int t = threadIdx.x;
    int v[4]; int loc = 0;
    #pragma unroll
    for (int k = 0; k < 4; k++) {
        int i = base + t * 4 + k;
        v[k] = (i < n) ? g_degi[i] : 0;
        if (i < n) g_dis[i] = rsqrtf((float)(v[k] + 1));
        loc += v[k];
    }
    sh[t] = loc;
    __syncthreads();
    for (int off = 1; off < 256; off <<= 1) {
        int x = sh[t];
        int y = (t >= off) ? sh[t - off] : 0;
        __syncthreads();
        sh[t] = x + y;
        __syncthreads();
    }
    int excl = (t == 0) ? 0 : sh[t - 1];
    if (t == 255) g_bsums[blockIdx.x] = sh[255];
    int run = excl;
    #pragma unroll
    for (int k = 0; k < 4; k++) {
        int i = base + t * 4 + k;
        if (i < n) g_rowptr[i] = run;
        run += v[k];
    }
}
__global__ void k_scan2(int nb) {
    __shared__ int sh[512];
    int t = threadIdx.x;
    sh[t] = (t < nb) ? g_bsums[t] : 0;
    __syncthreads();
    for (int off = 1; off < 512; off <<= 1) {
        int x = sh[t];
        int y = (t >= off) ? sh[t - off] : 0;
        __syncthreads();
        sh[t] = x + y;
        __syncthreads();
    }
    if (t < nb) g_bsums[t] = (t == 0) ? 0 : sh[t - 1];
}
__global__ void k_scan3(int n, int e) {
    int base = blockIdx.x * SCAN_CHUNK;
    int add = g_bsums[blockIdx.x];
    int t = threadIdx.x;
    #pragma unroll
    for (int k = 0; k < 4; k++) {
        int i = base + t * 4 + k;
        if (i < n) g_rowptr[i] += add;
    }
    if (blockIdx.x == 0 && t == 0) g_rowptr[n] = e;
}
__global__ void k_fill(const int* __restrict__ src, const int* __restrict__ dst, int e) {
    int i = blockIdx.x * blockDim.x + threadIdx.x;
    if (i < e) {
        int d = dst[i];
        int p = atomicAdd(&g_cursor[d], 1);
        g_csr[g_rowptr[d] + p] = src[i];
    }
}

// ---------------- prep: u = relu(affine(h)) * dis  (streaming, per-node) ----------------
template<int D, bool IN_A>
__global__ void k_prep(int n) {
    constexpr int NC = D / 4;
    const float4* in = (const float4*)(IN_A ? g_bufA : g_bufB);
    float4* out      = (float4*)(IN_A ? g_bufB : g_bufA);
    long long tot = (long long)n * NC;
    for (long long idx = (long long)blockIdx.x * blockDim.x + threadIdx.x;
         idx < tot; idx += (long long)gridDim.x * blockDim.x) {
        int node = (int)(idx / NC);
        int f = (int)(idx - (long long)node * NC);
        float dd = g_dis[node];
        float4 sc = ((const float4*)g_scale)[f];
        float4 sh = ((const float4*)g_shift)[f];
        float4 v = in[idx];
        float4 o;
        o.x = fmaxf(fmaf(sc.x, v.x, sh.x), 0.f) * dd;
        o.y = fmaxf(fmaf(sc.y, v.y, sh.y), 0.f) * dd;
        o.z = fmaxf(fmaf(sc.z, v.z, sh.z), 0.f) * dd;
        o.w = fmaxf(fmaf(sc.w, v.w, sh.w), 0.f) * dd;
        out[idx] = o;
    }
}

// ---------------- pure-sum gather, thread-per-node (D=8/16), packed adds ----------------
template<int D, bool IN_A, bool STATS>
__global__ void k_agg_tpn(int n) {
    constexpr int NC = D / 4;   // 16B chunks per node
    __shared__ float ss[8], ss2[8];
    int tid = threadIdx.x;
    if (STATS) {
        if (tid < 8) { ss[tid] = 0.f; ss2[tid] = 0.f; }
        __syncthreads();
    }
    const ulonglong2* in = (const ulonglong2*)(IN_A ? g_bufA : g_bufB);
    ulonglong2* out      = (ulonglong2*)(IN_A ? g_bufB : g_bufA);
    float ls[8], ls2[8];
    if (STATS) {
        #pragma unroll
        for (int c = 0; c < 8; c++) { ls[c] = 0.f; ls2[c] = 0.f; }
    }
    for (int d = blockIdx.x * blockDim.x + threadIdx.x; d < n; d += gridDim.x * blockDim.x) {
        ulonglong2 acc[NC];
        #pragma unroll
        for (int f = 0; f < NC; f++) acc[f] = in[(size_t)d * NC + f];   // self term u[d]
        int beg = g_rowptr[d], end = g_rowptr[d + 1];
        #pragma unroll 2
        for (int j = beg; j < end; j++) {
            int s = g_csr[j];
            #pragma unroll
            for (int f = 0; f < NC; f++) {
                ulonglong2 v = in[(size_t)s * NC + f];
                acc[f].x = f2add(acc[f].x, v.x);
                acc[f].y = f2add(acc[f].y, v.y);
            }
        }
        unsigned long long dd2 = f2pack(g_dis[d]);
        #pragma unroll
        for (int f = 0; f < NC; f++) {
            acc[f].x = f2mul(acc[f].x, dd2);
            acc[f].y = f2mul(acc[f].y, dd2);
            out[(size_t)d * NC + f] = acc[f];
            if (STATS) {
                float a, b;
                f2unpack(acc[f].x, a, b);
                ls[f * 4 + 0] += a; ls2[f * 4 + 0] += a * a;
                ls[f * 4 + 1] += b; ls2[f * 4 + 1] += b * b;
                f2unpack(acc[f].y, a, b);
                ls[f * 4 + 2] += a; ls2[f * 4 + 2] += a * a;
                ls[f * 4 + 3] += b; ls2[f * 4 + 3] += b * b;
            }
        }
    }
    if (STATS) {
        #pragma unroll
        for (int c = 0; c < 8; c++) {
            atomicAdd(&ss[c], ls[c]);
            atomicAdd(&ss2[c], ls2[c]);
        }
        __syncthreads();
        if (tid < 8) {
            atomicAdd(&g_stats[tid], (double)ss[tid]);
            atomicAdd(&g_stats[64 + tid], (double)ss2[tid]);
        }
    }
}

// ---------------- pure-sum gather, group variant (D=32/64), packed adds ----------------
template<int D, bool IN_A>
__global__ void k_agg_grp(int n) {
    constexpr int TPN = D / 4;          // lanes per node (16B each)
    constexpr int NPB = 256 / TPN;
    int tid = threadIdx.x;
    int grp = tid / TPN, lane = tid % TPN;
    const ulonglong2* in = (const ulonglong2*)(IN_A ? g_bufA : g_bufB);
    ulonglong2* out      = (ulonglong2*)(IN_A ? g_bufB : g_bufA);
    for (int d = blockIdx.x * NPB + grp; d < n; d += gridDim.x * NPB) {
        ulonglong2 acc = in[(size_t)d * TPN + lane];   // self term
        int beg = g_rowptr[d], end = g_rowptr[d + 1];
        #pragma unroll 4
        for (int j = beg; j < end; j++) {
            int s = g_csr[j];
            ulonglong2 v = in[(size_t)s * TPN + lane];
            acc.x = f2add(acc.x, v.x);
            acc.y = f2add(acc.y, v.y);
        }
        unsigned long long dd2 = f2pack(g_dis[d]);
        acc.x = f2mul(acc.x, dd2);
        acc.y = f2mul(acc.y, dd2);
        out[(size_t)d * TPN + lane] = acc;
    }
}

// ---------------- GEMM, 32-node tiles, W in registers ----------------
// MODE 0: xin -> bufB, epilogue *dis[node], no stats (layer 1)
// MODE 1: bufA -> bufB, fused BN stats
// MODE 2: bufB -> bufA, fused BN stats
template<int FI, int FO, int MODE>
__global__ void k_gemm2(const float* __restrict__ xin, const float* __restrict__ W, int n) {
    constexpr int TILE = 32;
    constexpr int NPB = 256 / FO;        // node-slots worked concurrently
    constexpr int NPT = TILE / NPB;      // nodes per thread per tile
    __shared__ float xs[TILE * FI];
    const float* zin = (MODE == 0) ? xin : (MODE == 1 ? g_bufA : g_bufB);
    float* hout      = (MODE == 0) ? g_bufB : (MODE == 1 ? g_bufB : g_bufA);
    int tid = threadIdx.x;
    int c = tid % FO, grp = tid / FO;
    float w[FI];
    #pragma unroll
    for (int k = 0; k < FI; k++) w[k] = W[k * FO + c];
    float s1 = 0.f, s2 = 0.f;
    int ntiles = (n + TILE - 1) / TILE;
    constexpr int NV = TILE * FI / 4;
    for (int t = blockIdx.x; t < ntiles; t += gridDim.x) {
        int base = t * TILE;
        __syncthreads();
        const float4* src4 = (const float4*)(zin + (size_t)base * FI);
        float4* xs4 = (float4*)xs;
        if (base + TILE <= n) {
            #pragma unroll
            for (int i = tid; i < NV; i += 256) xs4[i] = src4[i];
        } else {
            for (int i = tid; i < NV; i += 256) {
                int node = base + (i * 4) / FI;
                xs4[i] = (node < n) ? src4[i] : make_float4(0.f, 0.f, 0.f, 0.f);
            }
        }
        __syncthreads();
        #pragma unroll
        for (int u = 0; u < NPT; u++) {
            int slot = grp + u * NPB;
            int node = base + slot;
            if (node < n) {
                float acc = 0.f;
                const float4* row = (const float4*)(xs + slot * FI);
                #pragma unroll
                for (int k4 = 0; k4 < FI / 4; k4++) {
                    float4 z4 = row[k4];
                    acc = fmaf(z4.x, w[k4 * 4 + 0], acc);
                    acc = fmaf(z4.y, w[k4 * 4 + 1], acc);
                    acc = fmaf(z4.z, w[k4 * 4 + 2], acc);
                    acc = fmaf(z4.w, w[k4 * 4 + 3], acc);
                }
                if (MODE == 0) {
                    hout[(size_t)node * FO + c] = acc * g_dis[node];
                } else {
                    hout[(size_t)node * FO + c] = acc;
                    s1 += acc; s2 += acc * acc;
                }
            }
        }
    }
    if (MODE != 0) {
        __shared__ float r1[256], r2[256];
        r1[tid] = s1; r2[tid] = s2;
        __syncthreads();
        if (tid < FO) {
            float a = 0.f, b = 0.f;
            #pragma unroll
            for (int k = 0; k < NPB; k++) { a += r1[k * FO + tid]; b += r2[k * FO + tid]; }
            atomicAdd(&g_stats[tid], (double)a);
            atomicAdd(&g_stats[64 + tid], (double)b);
        }
    }
}

// scale = g*rsqrt(var+eps); shift = be - scale*mean (bias b cancels); zero stats
__global__ void k_bnfin(const float* __restrict__ g, const float* __restrict__ be,
                        int n, int fo) {
    int c = threadIdx.x;
    if (c >= 64) return;
    double s  = g_stats[c];
    double s2 = g_stats[64 + c];
    g_stats[c] = 0.0; g_stats[64 + c] = 0.0;
    if (c < fo) {
        double mean = s / n;
        double var  = s2 / n - mean * mean;
        float rs = rsqrtf((float)var + 1e-5f);
        float sc = g[c] * rs;
        g_scale[c] = sc;
        g_shift[c] = be[c] - sc * (float)mean;
    }
}

// ---------------- segment multi-aggregation (batch_idx sorted, coalesced float4) ----------------
__global__ void k_segagg(const int* __restrict__ bidx, int n) {
    int s = blockIdx.x;
    int tid = threadIdx.x;
    int lane = tid & 15;    // float4 channel chunk: channels 4*lane .. 4*lane+3
    int rowg = tid >> 4;    // 0..15
    __shared__ int se[2];
    if (tid < 2) {
        int target = s + tid;
        int lo = 0, hi = n;
        while (lo < hi) { int m = (lo + hi) >> 1; if (bidx[m] < target) lo = m + 1; else hi = m; }
        se[tid] = lo;
    }
    __syncthreads();
    int start = se[0], end = se[1];
    float4 sc = ((const float4*)g_scale)[lane];
    float4 sh = ((const float4*)g_shift)[lane];
    float4 sum = make_float4(0.f, 0.f, 0.f, 0.f);
    float4 sum2 = make_float4(0.f, 0.f, 0.f, 0.f);
    float4 mn = make_float4(INFINITY, INFINITY, INFINITY, INFINITY);
    float4 mx = make_float4(-INFINITY, -INFINITY, -INFINITY, -INFINITY);
    const float4* in = (const float4*)g_bufA;
    for (int r = start + rowg; r < end; r += 16) {
        float4 v = in[(size_t)r * 16 + lane];
        float a0 = fmaf(sc.x, v.x, sh.x);
        float a1 = fmaf(sc.y, v.y, sh.y);
        float a2 = fmaf(sc.z, v.z, sh.z);
        float a3 = fmaf(sc.w, v.w, sh.w);
        sum.x += a0; sum2.x += a0 * a0; mn.x = fminf(mn.x, a0); mx.x = fmaxf(mx.x, a0);
        sum.y += a1; sum2.y += a1 * a1; mn.y = fminf(mn.y, a1); mx.y = fmaxf(mx.y, a1);
        sum.z += a2; sum2.z += a2 * a2; mn.z = fminf(mn.z, a2); mx.z = fmaxf(mx.z, a2);
        sum.w += a3; sum2.w += a3 * a3; mn.w = fminf(mn.w, a3); mx.w = fmaxf(mx.w, a3);
    }
    __shared__ float4 rs1[256], rs2[256], rmn[256], rmx[256];
    rs1[tid] = sum; rs2[tid] = sum2; rmn[tid] = mn; rmx[tid] = mx;
    __syncthreads();
    if (rowg == 0) {
        #pragma unroll
        for (int k = 1; k < 16; k++) {
            float4 a = rs1[k * 16 + lane], b = rs2[k * 16 + lane];
            float4 c = rmn[k * 16 + lane], d = rmx[k * 16 + lane];
            sum.x += a.x; sum.y += a.y; sum.z += a.z; sum.w += a.w;
            sum2.x += b.x; sum2.y += b.y; sum2.z += b.z; sum2.w += b.w;
            mn.x = fminf(mn.x, c.x); mn.y = fminf(mn.y, c.y);
            mn.z = fminf(mn.z, c.z); mn.w = fminf(mn.w, c.w);
            mx.x = fmaxf(mx.x, d.x); mx.y = fmaxf(mx.y, d.y);
            mx.z = fmaxf(mx.z, d.z); mx.w = fmaxf(mx.w, d.w);
        }
        float cnt = fmaxf((float)(end - start), 1.0f);
        float inv = 1.0f / cnt;
        float4 mean, stdv;
        mean.x = sum.x * inv; mean.y = sum.y * inv;
        mean.z = sum.z * inv; mean.w = sum.w * inv;
        stdv.x = sqrtf(fmaxf(sum2.x * inv - mean.x * mean.x, 0.f) + 1e-5f);
        stdv.y = sqrtf(fmaxf(sum2.y * inv - mean.y * mean.y, 0.f) + 1e-5f);
        stdv.z = sqrtf(fmaxf(sum2.z * inv - mean.z * mean.z, 0.f) + 1e-5f);
        stdv.w = sqrtf(fmaxf(sum2.w * inv - mean.w * mean.w, 0.f) + 1e-5f);
        float4* sf = (float4*)&g_segfeat[s * 256];
        sf[lane]      = mean;
        sf[16 + lane] = mn;
        sf[32 + lane] = mx;
        sf[48 + lane] = stdv;
    }
}

// ---------------- projection: [S,256] @ Wp[256,64] + bp ----------------
__global__ void k_proj(const float* __restrict__ Wp, const float* __restrict__ bp) {
    int idx = blockIdx.x * blockDim.x + threadIdx.x;
    if (idx >= S_SEG * 64) return;
    int s = idx >> 6, c = idx & 63;
    float acc = bp[c];
    const float* f = &g_segfeat[s * 256];
    #pragma unroll 8
    for (int k = 0; k < 256; k++)
        acc = fmaf(f[k], Wp[k * 64 + c], acc);
    g_proj[idx] = acc;
}

// ---------------- pack: out[b,c,j,i] = proj[offs[b] + i*14+j, c] (masked) ----------------
__global__ void k_pack(const int* __restrict__ num_sp, float* __restrict__ out) {
    int idx = blockIdx.x * blockDim.x + threadIdx.x;
    if (idx >= B_IMG * 64 * 196) return;
    int b   = idx / (64 * 196);
    int rem = idx - b * (64 * 196);
    int c   = rem / 196;
    int ji  = rem - c * 196;
    int j = ji / 14, ii = ji - j * 14;
    int p = ii * 14 + j;
    int ns = num_sp[b];
    int off = 0;
    for (int q = 0; q < b; q++) off += num_sp[q];
    float v = 0.f;
    if (p < ns) {
        int row = off + p;
        if (row > S_SEG - 1) row = S_SEG - 1;
        v = g_proj[row * 64 + c];
    }
    out[idx] = v;
}

// ---------------- host orchestration ----------------
extern "C" void kernel_launch(void* const* d_in, const int* in_sizes, int n_in,
                              void* d_out, int out_size) {
    const float* x        = (const float*)d_in[0];
    const int*   ei       = (const int*)d_in[1];
    const int*   batchidx = (const int*)d_in[2];
    const int*   num_sp   = (const int*)d_in[3];
    const int n = in_sizes[2];
    const int e = in_sizes[1] / 2;
    const int* src = ei;
    const int* dst = ei + e;

    const float* W[5], *g[5], *be[5];
    for (int i = 0; i < 5; i++) {
        W[i]  = (const float*)d_in[4 + 4 * i];
        g[i]  = (const float*)d_in[6 + 4 * i];
        be[i] = (const float*)d_in[7 + 4 * i];
    }
    const float* Wp = (const float*)d_in[24];
    const float* bp = (const float*)d_in[25];
    float* out = (float*)d_out;

    // degrees + CSR build (once per launch)
    k_zero_nodes<<<(n + 255) / 256, 256>>>(n);
    k_deg_count<<<(e + 255) / 256, 256>>>(dst, e);
    int nb = (n + SCAN_CHUNK - 1) / SCAN_CHUNK;
    k_scan1<<<nb, 256>>>(n);
    k_scan2<<<1, 512>>>(nb);
    k_scan3<<<nb, 256>>>(n, e);
    k_fill<<<(e + 255) / 256, 256>>>(src, dst, e);

    const int AB = 1184;   // agg/prep grid
    const int GB = 1184;   // gemm grid

    // L1: GEMM (24->8, writes u=t*dis to B), pure-sum agg B->A (stats fused)
    k_gemm2<24, 8, 0><<<GB, 256>>>(x, W[0], n);
    k_agg_tpn<8, false, true><<<AB, 256>>>(n);
    k_bnfin<<<1, 64>>>(g[0], be[0], n, 8);

    // L2: prep A->B (dim 8), agg B->A, gemm 8->16 A->B
    k_prep<8, true><<<AB, 256>>>(n);
    k_agg_tpn<8, false, false><<<AB, 256>>>(n);
    k_gemm2<8, 16, 1><<<GB, 256>>>(nullptr, W[1], n);
    k_bnfin<<<1, 64>>>(g[1], be[1], n, 16);

    // L3: prep B->A (dim 16), agg A->B, gemm 16->32 B->A
    k_prep<16, false><<<AB, 256>>>(n);
    k_agg_tpn<16, true, false><<<AB, 256>>>(n);
    k_gemm2<16, 32, 2><<<GB, 256>>>(nullptr, W[2], n);
    k_bnfin<<<1, 64>>>(g[2], be[2], n, 32);

    // L4: prep A->B (dim 32), agg B->A, gemm 32->64 A->B
    k_prep<32, true><<<AB, 256>>>(n);
    k_agg_grp<32, false><<<AB, 256>>>(n);
    k_gemm2<32, 64, 1><<<GB, 256>>>(nullptr, W[3], n);
    k_bnfin<<<1, 64>>>(g[3], be[3], n, 64);

    // L5: prep B->A (dim 64), agg A->B, gemm 64->64 B->A  (h5 in A)
    k_prep<64, false><<<AB, 256>>>(n);
    k_agg_grp<64, true><<<AB, 256>>>(n);
    k_gemm2<64, 64, 2><<<GB, 256>>>(nullptr, W[4], n);
    k_bnfin<<<1, 64>>>(g[4], be[4], n, 64);

    // segment aggregation (applies L5 BN affine, no ReLU)
    k_segagg<<<S_SEG, 256>>>(batchidx, n);
    k_proj<<<(S_SEG * 64 + 255) / 256, 256>>>(Wp, bp);
    k_pack<<<(B_IMG * 64 * 196 + 255) / 256, 256>>>(num_sp, out);
}